// round 13
// baseline (speedup 1.0000x reference)
#include <cuda_runtime.h>

#define DEV_INLINE __device__ __forceinline__
typedef unsigned long long ull;

constexpr int C  = 8;
constexpr int K  = 64;
constexpr int NN = 2048;

// ---- per-(c,k) repacked blob layout (floats) ----
// s/t weight banks padded 16 floats (=16 banks) apart: s-lanes and t-lanes of
// one warp instruction hit disjoint bank sets.
constexpr int BLOB = 5632;               // 22528 B = 1408 x 16B chunks; /64 thr = 22
constexpr int W1S = 0;                   // [64][20] stride-padded, cols 0..15 valid
constexpr int W1T = 1296;                // = W1S + 1280 + 16 (bank shift)
constexpr int W2S = 2592;                // transposed [i][r], stride 20
constexpr int W2T = 3888;                // = W2S + 1280 + 16
constexpr int B1S = 5168, B1T = 5236;    // δ68 ≡ 4 mod 32 banks
constexpr int B2S = 5300, B2T = 5316;    // passive order
constexpr int ANE = 5332;                // [act 16 | pas 16] exp(-s)
constexpr int ANF = 5364;                // [act 16 | pas 16] -t*exp(-s)
constexpr int ASUM = 5396;

__device__ float g_blob[C * K * BLOB];
__device__ float g_Bm[C * NN];
__device__ float g_Sn[C * C];

// ---------- packed f32x2 helpers ----------
DEV_INLINE ull pack2(float lo, float hi) {
    ull r; asm("mov.b64 %0, {%1,%2};" : "=l"(r) : "f"(lo), "f"(hi)); return r;
}
DEV_INLINE void unpack2(ull v, float& lo, float& hi) {
    asm("mov.b64 {%0,%1}, %2;" : "=f"(lo), "=f"(hi) : "l"(v));
}
DEV_INLINE ull ffma2(ull a, ull b, ull c) {
    ull d; asm("fma.rn.f32x2 %0, %1, %2, %3;" : "=l"(d) : "l"(a), "l"(b), "l"(c)); return d;
}
DEV_INLINE ull add2(ull a, ull b) {
    ull d; asm("add.rn.f32x2 %0, %1, %2;" : "=l"(d) : "l"(a), "l"(b)); return d;
}
DEV_INLINE ull mul2(ull a, ull b) {
    ull d; asm("mul.rn.f32x2 %0, %1, %2;" : "=l"(d) : "l"(a), "l"(b)); return d;
}
DEV_INLINE ull neg2(ull a) { return a ^ 0x8000000080000000ULL; }

// ---------- cp.async staging (64-thread block: 22 chunks each) ----------
DEV_INLINE void stage(float* sdst, const float* gsrc, int tid) {
    unsigned sa = (unsigned)__cvta_generic_to_shared(sdst);
    #pragma unroll
    for (int i = 0; i < 22; i++) {
        int ch = tid + i * 64;
        asm volatile("cp.async.cg.shared.global [%0], [%1], 16;"
                     :: "r"(sa + ch * 16), "l"(gsrc + ch * 4));
    }
    asm volatile("cp.async.commit_group;");
}
DEV_INLINE void wait_stage() {
    asm volatile("cp.async.wait_group 0;" ::: "memory");
}

// ---------- repack: gather/compact/transpose weights once ----------
__global__ void __launch_bounds__(128)
repack_kernel(const float* __restrict__ sW1, const float* __restrict__ sb1,
              const float* __restrict__ sW2, const float* __restrict__ sb2,
              const float* __restrict__ tW1, const float* __restrict__ tb1,
              const float* __restrict__ tW2, const float* __restrict__ tb2,
              const float* __restrict__ anS, const float* __restrict__ anT)
{
    const int ck = blockIdx.x;          // c*64+k
    const int k = ck & 63;
    const int A = k & 1, PO = 1 - A;    // active / passive parity
    float* B = g_blob + (size_t)ck * BLOB;
    const int tid = threadIdx.x;
    const size_t wo = (size_t)ck * 2048;

    for (int idx = tid; idx < 1024; idx += 128) {
        int i = idx >> 4, j = idx & 15;
        B[W1S + i * 20 + j] = sW1[wo + i * 32 + 2 * j + A];
        B[W1T + i * 20 + j] = tW1[wo + i * 32 + 2 * j + A];
        B[W2S + i * 20 + j] = sW2[wo + (2 * j + PO) * 64 + i];
        B[W2T + i * 20 + j] = tW2[wo + (2 * j + PO) * 64 + i];
    }
    if (tid < 64) {
        B[B1S + tid] = sb1[ck * 64 + tid];
        B[B1T + tid] = tb1[ck * 64 + tid];
    } else if (tid < 80) {
        int r = tid - 64;
        B[B2S + r] = sb2[ck * 32 + 2 * r + PO];
        B[B2T + r] = tb2[ck * 32 + 2 * r + PO];
    } else if (tid < 112) {
        int q = tid - 80;               // 0..31: [act 16 | pas 16]
        int dim = (q < 16) ? (2 * q + A) : (2 * (q - 16) + PO);
        float a = anS[ck * 32 + dim];
        float t = anT[ck * 32 + dim];
        float e = __expf(-a);
        B[ANE + q] = e;
        B[ANF + q] = -t * e;
    } else if (tid == 112) {
        float s = 0.f;
        for (int d = 0; d < 32; d++) s += anS[ck * 32 + d];
        B[ASUM] = s;
    }
}

// ---------- one inverse layer ----------
// 8 threads per node pair: q = hidden quarter (tid&3), m = mlp select (0=s,1=t).
// Each thread: 2 nodes, one MLP, 16 hidden units. Butterfly over q, exchange
// e^{-s} <-> t over m. Separate log-dets ld0/ld1 per node.
DEV_INLINE void layer_compute(const float* __restrict__ sb, int q, int m,
                              ull (&a0)[8], ull (&p0)[8],
                              ull (&a1)[8], ull (&p1)[8],
                              float& ld0, float& ld1)
{
    // ActNorm inverse (E/F stored in act|pas order) — all threads, both nodes
    const ull* E = (const ull*)(sb + ANE);
    const ull* F = (const ull*)(sb + ANF);
    #pragma unroll
    for (int j = 0; j < 8; j++) {
        ull e = E[j], f = F[j];
        a0[j] = ffma2(a0[j], e, f);
        a1[j] = ffma2(a1[j], e, f);
        ull e2 = E[8 + j], f2 = F[8 + j];
        p0[j] = ffma2(p0[j], e2, f2);
        p1[j] = ffma2(p1[j], e2, f2);
    }
    float asum = sb[ASUM];
    ld0 -= asum;
    ld1 -= asum;

    // this thread's MLP weight banks (s/t bank-shifted by 16)
    const float* w1 = sb + (m ? W1T : W1S);
    const float* w2 = sb + (m ? W2T : W2S);
    const float* b1 = sb + (m ? B1T : B1S);
    const ull*   b2 = (const ull*)(sb + (m ? B2T : B2S));

    // 16 outputs as 8 packed pairs, per node
    ull acc0[8], acc1[8];
    #pragma unroll
    for (int j = 0; j < 8; j++) {
        ull b = (q == 0) ? b2[j] : 0ULL;
        acc0[j] = b; acc1[j] = b;
    }

    #pragma unroll 4
    for (int il = 0; il < 16; il++) {
        const int gi = il * 4 + q;                  // this thread's hidden unit
        const ulonglong2* r1 = (const ulonglong2*)(w1 + gi * 20);
        ull h0 = pack2(b1[gi], 0.f);
        ull h1 = h0;
        #pragma unroll
        for (int ch = 0; ch < 2; ch++) {
            ulonglong2 wa = r1[2 * ch], wb = r1[2 * ch + 1];
            h0 = ffma2(wa.x, a0[4 * ch],     h0);
            h0 = ffma2(wa.y, a0[4 * ch + 1], h0);
            h0 = ffma2(wb.x, a0[4 * ch + 2], h0);
            h0 = ffma2(wb.y, a0[4 * ch + 3], h0);
            h1 = ffma2(wa.x, a1[4 * ch],     h1);
            h1 = ffma2(wa.y, a1[4 * ch + 1], h1);
            h1 = ffma2(wb.x, a1[4 * ch + 2], h1);
            h1 = ffma2(wb.y, a1[4 * ch + 3], h1);
        }
        float x0, x1;
        unpack2(h0, x0, x1); float hv0 = fmaxf(x0 + x1, 0.f);
        unpack2(h1, x0, x1); float hv1 = fmaxf(x0 + x1, 0.f);
        ull h0p = pack2(hv0, hv0), h1p = pack2(hv1, hv1);

        const ulonglong2* r2 = (const ulonglong2*)(w2 + gi * 20);
        #pragma unroll
        for (int ch = 0; ch < 4; ch++) {
            ulonglong2 w = r2[ch];
            acc0[2 * ch]     = ffma2(w.x, h0p, acc0[2 * ch]);
            acc0[2 * ch + 1] = ffma2(w.y, h0p, acc0[2 * ch + 1]);
            acc1[2 * ch]     = ffma2(w.x, h1p, acc1[2 * ch]);
            acc1[2 * ch + 1] = ffma2(w.y, h1p, acc1[2 * ch + 1]);
        }
    }

    // butterfly over the 4 quarter-threads (same m)
    #pragma unroll
    for (int j = 0; j < 8; j++) {
        acc0[j] = add2(acc0[j], __shfl_xor_sync(0xffffffffu, acc0[j], 1));
        acc0[j] = add2(acc0[j], __shfl_xor_sync(0xffffffffu, acc0[j], 2));
        acc1[j] = add2(acc1[j], __shfl_xor_sync(0xffffffffu, acc1[j], 1));
        acc1[j] = add2(acc1[j], __shfl_xor_sync(0xffffffffu, acc1[j], 2));
    }

    // exchange across m (xor 4): s-thread sends e^{-s}, t-thread sends t.
    // Both sides then apply the identical passive update.
    #pragma unroll
    for (int j = 0; j < 8; j++) {
        {   // node 0
            float x0, x1;
            unpack2(acc0[j], x0, x1);
            ull e2o = pack2(__expf(-x0), __expf(-x1));   // valid on m==0
            if (m == 0) ld0 -= (x0 + x1);                // node-0 log-det only
            ull send = (m == 0) ? e2o : acc0[j];
            ull recv = __shfl_xor_sync(0xffffffffu, send, 4);
            ull e2v  = (m == 0) ? e2o : recv;
            ull tv   = (m == 0) ? recv : acc0[j];
            p0[j] = ffma2(p0[j], e2v, neg2(mul2(tv, e2v)));
        }
        {   // node 1
            float x0, x1;
            unpack2(acc1[j], x0, x1);
            ull e2o = pack2(__expf(-x0), __expf(-x1));
            if (m == 0) ld1 -= (x0 + x1);                // node-1 log-det only
            ull send = (m == 0) ? e2o : acc1[j];
            ull recv = __shfl_xor_sync(0xffffffffu, send, 4);
            ull e2v  = (m == 0) ? e2o : recv;
            ull tv   = (m == 0) ? recv : acc1[j];
            p1[j] = ffma2(p1[j], e2v, neg2(mul2(tv, e2v)));
        }
    }
}

__global__ void __launch_bounds__(64)
flow_kernel(const float* __restrict__ nodes,
            const float* __restrict__ loc, const float* __restrict__ lsc)
{
    __shared__ __align__(16) float sbuf[BLOB];   // single buffer: 22.5 KB
    const int tid  = threadIdx.x;
    const int q    = tid & 3;            // hidden quarter
    const int m    = (tid >> 2) & 1;     // 0 = s-MLP, 1 = t-MLP
    const int slot = tid >> 3;           // 0..7
    const int c    = blockIdx.y;
    const int n0   = blockIdx.x * 16 + slot;
    const int n1   = n0 + 8;

    // z packed by parity: ze[j]=(dims 4j,4j+2), zo[j]=(4j+1,4j+3)
    ull ze0[8], zo0[8], ze1[8], zo1[8];
    {
        const float4* np = (const float4*)(nodes + (size_t)n0 * 32);
        #pragma unroll
        for (int j = 0; j < 8; j++) {
            float4 v = np[j];
            ze0[j] = pack2(v.x, v.z); zo0[j] = pack2(v.y, v.w);
        }
        np = (const float4*)(nodes + (size_t)n1 * 32);
        #pragma unroll
        for (int j = 0; j < 8; j++) {
            float4 v = np[j];
            ze1[j] = pack2(v.x, v.z); zo1[j] = pack2(v.y, v.w);
        }
    }
    float ld0 = 0.f, ld1 = 0.f;

    const float* gb = g_blob + (size_t)(c * 64) * BLOB;

    stage(sbuf, gb + (size_t)63 * BLOB, tid);
    wait_stage();
    __syncthreads();

    #pragma unroll 1
    for (int k = 63; k > 0; k -= 2) {
        // layer k (odd): active = odd dims
        layer_compute(sbuf, q, m, zo0, ze0, zo1, ze1, ld0, ld1);
        __syncthreads();
        stage(sbuf, gb + (size_t)(k - 1) * BLOB, tid);
        wait_stage();
        __syncthreads();
        // layer k-1 (even): active = even dims
        layer_compute(sbuf, q, m, ze0, zo0, ze1, zo1, ld0, ld1);
        if (k >= 3) {
            __syncthreads();
            stage(sbuf, gb + (size_t)(k - 2) * BLOB, tid);
            wait_stage();
            __syncthreads();
        }
    }

    // DiagGaussian log_prob (redundant; written by q==0 && m==0)
    float acc0 = 0.f, acc1 = 0.f;
    const float* lp = loc + c * 32;
    const float* sp = lsc + c * 32;
    #pragma unroll
    for (int j = 0; j < 8; j++) {
        float e0, e1, o0, o1;
        float z40[4], z41[4];
        unpack2(ze0[j], e0, e1); unpack2(zo0[j], o0, o1);
        z40[0] = e0; z40[1] = o0; z40[2] = e1; z40[3] = o1;
        unpack2(ze1[j], e0, e1); unpack2(zo1[j], o0, o1);
        z41[0] = e0; z41[1] = o0; z41[2] = e1; z41[3] = o1;
        #pragma unroll
        for (int b = 0; b < 4; b++) {
            int d = 4 * j + b;
            float ls = __ldg(sp + d);
            float es = __expf(-ls);
            float lc = __ldg(lp + d);
            float u0 = (z40[b] - lc) * es;
            float u1 = (z41[b] - lc) * es;
            acc0 += ls + 0.5f * u0 * u0;
            acc1 += ls + 0.5f * u1 * u1;
        }
    }
    if (q == 0 && m == 0) {
        g_Bm[c * NN + n0] = __expf(ld0 - 29.406037829f - acc0);
        g_Bm[c * NN + n1] = __expf(ld1 - 29.406037829f - acc1);
    }
}

// Fold L1 row-normalizers and softmax-normalized S into one 8x8 matrix.
__global__ void norm_kernel(const float* __restrict__ S_unc)
{
    __shared__ float sh_r[8];
    __shared__ float sh_e[64];
    const int tid = threadIdx.x;
    const int w = tid >> 5, lane = tid & 31;

    float s = 0.f;
    for (int i = lane; i < NN; i += 32) s += g_Bm[w * NN + i];
    #pragma unroll
    for (int o = 16; o; o >>= 1) s += __shfl_xor_sync(0xffffffffu, s, o);
    if (lane == 0) sh_r[w] = fmaxf(s, 1e-12f);
    if (tid < 64) sh_e[tid] = expf(S_unc[tid]);
    __syncthreads();
    if (tid < 64) {
        float tot = 0.f;
        #pragma unroll
        for (int i = 0; i < 64; i++) tot += sh_e[i];
        int c1 = tid >> 3, c2 = tid & 7;
        g_Sn[tid] = sh_e[tid] / (tot * sh_r[c1] * sh_r[c2]);
    }
}

__global__ void __launch_bounds__(256)
out_kernel(float* __restrict__ out)
{
    __shared__ float B1[8][64];
    __shared__ float B2[8][64];
    __shared__ float T2[8][64];
    const int tid = threadIdx.x;
    const int n10 = blockIdx.y * 64;
    const int n20 = blockIdx.x * 64;

    for (int t = tid; t < 512; t += 256) {
        int cc = t >> 6, j = t & 63;
        B1[cc][j] = g_Bm[cc * NN + n10 + j];
        B2[cc][j] = g_Bm[cc * NN + n20 + j];
    }
    __syncthreads();
    if (tid < 64) {
        #pragma unroll
        for (int c1 = 0; c1 < 8; c1++) {
            float a = 0.f;
            #pragma unroll
            for (int c2 = 0; c2 < 8; c2++)
                a = fmaf(g_Sn[c1 * 8 + c2], B2[c2][tid], a);
            T2[c1][tid] = a;
        }
    }
    __syncthreads();

    const int ty = tid >> 4, tx = tid & 15;
    float bv[4][8], tv[8][4];
    #pragma unroll
    for (int cc = 0; cc < 8; cc++) {
        #pragma unroll
        for (int p = 0; p < 4; p++) {
            bv[p][cc] = B1[cc][ty * 4 + p];
            tv[cc][p] = T2[cc][tx * 4 + p];
        }
    }
    #pragma unroll
    for (int p = 0; p < 4; p++) {
        float4 o = {0.f, 0.f, 0.f, 0.f};
        #pragma unroll
        for (int cc = 0; cc < 8; cc++) {
            o.x = fmaf(bv[p][cc], tv[cc][0], o.x);
            o.y = fmaf(bv[p][cc], tv[cc][1], o.y);
            o.z = fmaf(bv[p][cc], tv[cc][2], o.z);
            o.w = fmaf(bv[p][cc], tv[cc][3], o.w);
        }
        *((float4*)(out + (size_t)(n10 + ty * 4 + p) * NN + n20 + tx * 4)) = o;
    }
}

extern "C" void kernel_launch(void* const* d_in, const int* in_sizes, int n_in,
                              void* d_out, int out_size)
{
    const float* nodes = (const float*)d_in[0];
    const float* sW1   = (const float*)d_in[1];
    const float* sb1   = (const float*)d_in[2];
    const float* sW2   = (const float*)d_in[3];
    const float* sb2   = (const float*)d_in[4];
    const float* tW1   = (const float*)d_in[5];
    const float* tb1   = (const float*)d_in[6];
    const float* tW2   = (const float*)d_in[7];
    const float* tb2   = (const float*)d_in[8];
    const float* anS   = (const float*)d_in[9];
    const float* anT   = (const float*)d_in[10];
    const float* loc   = (const float*)d_in[11];
    const float* lsc   = (const float*)d_in[12];
    const float* S_unc = (const float*)d_in[13];
    float* out = (float*)d_out;

    repack_kernel<<<C * K, 128>>>(sW1, sb1, sW2, sb2, tW1, tb1, tW2, tb2, anS, anT);
    dim3 fg(NN / 16, C);                 // 128 x 8 = 1024 blocks, 64 thr, npt=2 q*m
    flow_kernel<<<fg, 64>>>(nodes, loc, lsc);
    norm_kernel<<<1, 256>>>(S_unc);
    dim3 og(NN / 64, NN / 64);
    out_kernel<<<og, 256>>>(out);
}

// round 14
// speedup vs baseline: 1.4185x; 1.4185x over previous
#include <cuda_runtime.h>

#define DEV_INLINE __device__ __forceinline__
typedef unsigned long long ull;

constexpr int C  = 8;
constexpr int K  = 64;
constexpr int NN = 2048;
constexpr int BPC = 74;                  // blocks per component: 8*74=592 = 4*148

// ---- per-(c,k) repacked blob layout (floats) ----
// s/t weight banks padded 16 floats (=16 banks) apart: s-lanes and t-lanes of
// one warp instruction hit disjoint bank sets.
constexpr int BLOB = 5632;               // 22528 B = 1408 x 16B chunks; /64 thr = 22
constexpr int W1S = 0;                   // [64][20] stride-padded, cols 0..15 valid
constexpr int W1T = 1296;                // = W1S + 1280 + 16 (bank shift)
constexpr int W2S = 2592;                // transposed [i][r], stride 20
constexpr int W2T = 3888;                // = W2S + 1280 + 16
constexpr int B1S = 5168, B1T = 5236;    // δ68 ≡ 4 mod 32 banks
constexpr int B2S = 5300, B2T = 5316;    // passive order
constexpr int ANE = 5332;                // [act 16 | pas 16] exp(-s)
constexpr int ANF = 5364;                // [act 16 | pas 16] -t*exp(-s)
constexpr int ASUM = 5396;

__device__ float g_blob[C * K * BLOB];
__device__ float g_Bm[C * NN];
__device__ float g_Sn[C * C];

// ---------- packed f32x2 helpers ----------
DEV_INLINE ull pack2(float lo, float hi) {
    ull r; asm("mov.b64 %0, {%1,%2};" : "=l"(r) : "f"(lo), "f"(hi)); return r;
}
DEV_INLINE void unpack2(ull v, float& lo, float& hi) {
    asm("mov.b64 {%0,%1}, %2;" : "=f"(lo), "=f"(hi) : "l"(v));
}
DEV_INLINE ull ffma2(ull a, ull b, ull c) {
    ull d; asm("fma.rn.f32x2 %0, %1, %2, %3;" : "=l"(d) : "l"(a), "l"(b), "l"(c)); return d;
}
DEV_INLINE ull add2(ull a, ull b) {
    ull d; asm("add.rn.f32x2 %0, %1, %2;" : "=l"(d) : "l"(a), "l"(b)); return d;
}
DEV_INLINE ull mul2(ull a, ull b) {
    ull d; asm("mul.rn.f32x2 %0, %1, %2;" : "=l"(d) : "l"(a), "l"(b)); return d;
}
DEV_INLINE ull neg2(ull a) { return a ^ 0x8000000080000000ULL; }

// ---------- cp.async staging (64-thread block: 22 chunks each) ----------
DEV_INLINE void stage(float* sdst, const float* gsrc, int tid) {
    unsigned sa = (unsigned)__cvta_generic_to_shared(sdst);
    #pragma unroll
    for (int i = 0; i < 22; i++) {
        int ch = tid + i * 64;
        asm volatile("cp.async.cg.shared.global [%0], [%1], 16;"
                     :: "r"(sa + ch * 16), "l"(gsrc + ch * 4));
    }
    asm volatile("cp.async.commit_group;");
}
DEV_INLINE void wait_stage() {
    asm volatile("cp.async.wait_group 0;" ::: "memory");
}

// ---------- repack: gather/compact/transpose weights once ----------
__global__ void __launch_bounds__(128)
repack_kernel(const float* __restrict__ sW1, const float* __restrict__ sb1,
              const float* __restrict__ sW2, const float* __restrict__ sb2,
              const float* __restrict__ tW1, const float* __restrict__ tb1,
              const float* __restrict__ tW2, const float* __restrict__ tb2,
              const float* __restrict__ anS, const float* __restrict__ anT)
{
    const int ck = blockIdx.x;          // c*64+k
    const int k = ck & 63;
    const int A = k & 1, PO = 1 - A;    // active / passive parity
    float* B = g_blob + (size_t)ck * BLOB;
    const int tid = threadIdx.x;
    const size_t wo = (size_t)ck * 2048;

    for (int idx = tid; idx < 1024; idx += 128) {
        int i = idx >> 4, j = idx & 15;
        B[W1S + i * 20 + j] = sW1[wo + i * 32 + 2 * j + A];
        B[W1T + i * 20 + j] = tW1[wo + i * 32 + 2 * j + A];
        B[W2S + i * 20 + j] = sW2[wo + (2 * j + PO) * 64 + i];
        B[W2T + i * 20 + j] = tW2[wo + (2 * j + PO) * 64 + i];
    }
    if (tid < 64) {
        B[B1S + tid] = sb1[ck * 64 + tid];
        B[B1T + tid] = tb1[ck * 64 + tid];
    } else if (tid < 80) {
        int r = tid - 64;
        B[B2S + r] = sb2[ck * 32 + 2 * r + PO];
        B[B2T + r] = tb2[ck * 32 + 2 * r + PO];
    } else if (tid < 112) {
        int q = tid - 80;               // 0..31: [act 16 | pas 16]
        int dim = (q < 16) ? (2 * q + A) : (2 * (q - 16) + PO);
        float a = anS[ck * 32 + dim];
        float t = anT[ck * 32 + dim];
        float e = __expf(-a);
        B[ANE + q] = e;
        B[ANF + q] = -t * e;
    } else if (tid == 112) {
        float s = 0.f;
        for (int d = 0; d < 32; d++) s += anS[ck * 32 + d];
        B[ASUM] = s;
    }
}

// ---------- one inverse layer ----------
// 8 threads per 4-node group: q = hidden quarter (tid&3), m = mlp (0=s,1=t).
// Each thread: 4 nodes, one MLP, 16 hidden units. Butterfly over q, exchange
// e^{-s} <-> t over m. Per-node log-dets.
DEV_INLINE void layer_compute(const float* __restrict__ sb, int q, int m,
                              ull (&a)[4][8], ull (&p)[4][8], float (&ld)[4])
{
    // ActNorm inverse (E/F stored in act|pas order) — all threads, all nodes
    const ull* E = (const ull*)(sb + ANE);
    const ull* F = (const ull*)(sb + ANF);
    #pragma unroll
    for (int j = 0; j < 8; j++) {
        ull e = E[j], f = F[j];
        ull e2 = E[8 + j], f2 = F[8 + j];
        #pragma unroll
        for (int n = 0; n < 4; n++) {
            a[n][j] = ffma2(a[n][j], e, f);
            p[n][j] = ffma2(p[n][j], e2, f2);
        }
    }
    float asum = sb[ASUM];
    #pragma unroll
    for (int n = 0; n < 4; n++) ld[n] -= asum;

    // this thread's MLP weight banks (s/t bank-shifted by 16)
    const float* w1 = sb + (m ? W1T : W1S);
    const float* w2 = sb + (m ? W2T : W2S);
    const float* b1 = sb + (m ? B1T : B1S);
    const ull*   b2 = (const ull*)(sb + (m ? B2T : B2S));

    // 16 outputs as 8 packed pairs, per node
    ull acc[4][8];
    #pragma unroll
    for (int j = 0; j < 8; j++) {
        ull b = (q == 0) ? b2[j] : 0ULL;
        #pragma unroll
        for (int n = 0; n < 4; n++) acc[n][j] = b;
    }

    #pragma unroll 2
    for (int il = 0; il < 16; il++) {
        const int gi = il * 4 + q;                  // this thread's hidden unit
        const ulonglong2* r1 = (const ulonglong2*)(w1 + gi * 20);
        float b1v = b1[gi];
        ull h[4];
        #pragma unroll
        for (int n = 0; n < 4; n++) h[n] = pack2(b1v, 0.f);
        #pragma unroll
        for (int ch = 0; ch < 2; ch++) {
            ulonglong2 wa = r1[2 * ch], wb = r1[2 * ch + 1];
            #pragma unroll
            for (int n = 0; n < 4; n++) {
                h[n] = ffma2(wa.x, a[n][4 * ch],     h[n]);
                h[n] = ffma2(wa.y, a[n][4 * ch + 1], h[n]);
                h[n] = ffma2(wb.x, a[n][4 * ch + 2], h[n]);
                h[n] = ffma2(wb.y, a[n][4 * ch + 3], h[n]);
            }
        }
        ull hp[4];
        #pragma unroll
        for (int n = 0; n < 4; n++) {
            float x0, x1; unpack2(h[n], x0, x1);
            float hv = fmaxf(x0 + x1, 0.f);
            hp[n] = pack2(hv, hv);
        }
        const ulonglong2* r2 = (const ulonglong2*)(w2 + gi * 20);
        #pragma unroll
        for (int ch = 0; ch < 4; ch++) {
            ulonglong2 w = r2[ch];
            #pragma unroll
            for (int n = 0; n < 4; n++) {
                acc[n][2 * ch]     = ffma2(w.x, hp[n], acc[n][2 * ch]);
                acc[n][2 * ch + 1] = ffma2(w.y, hp[n], acc[n][2 * ch + 1]);
            }
        }
    }

    // butterfly over q (xor 1,2), then exchange e^{-s} <-> t over m (xor 4);
    // both m-lanes apply the identical passive update.
    #pragma unroll
    for (int j = 0; j < 8; j++) {
        #pragma unroll
        for (int n = 0; n < 4; n++) {
            ull v = acc[n][j];
            v = add2(v, __shfl_xor_sync(0xffffffffu, v, 1));
            v = add2(v, __shfl_xor_sync(0xffffffffu, v, 2));
            float x0, x1; unpack2(v, x0, x1);
            ull e2o = pack2(__expf(-x0), __expf(-x1));    // valid on m==0
            if (m == 0) ld[n] -= (x0 + x1);
            ull send = (m == 0) ? e2o : v;
            ull recv = __shfl_xor_sync(0xffffffffu, send, 4);
            ull e2v  = (m == 0) ? e2o : recv;
            ull tv   = (m == 0) ? recv : v;
            p[n][j] = ffma2(p[n][j], e2v, neg2(mul2(tv, e2v)));
        }
    }
}

__global__ void __launch_bounds__(64)
flow_kernel(const float* __restrict__ nodes,
            const float* __restrict__ loc, const float* __restrict__ lsc)
{
    __shared__ __align__(16) float sbuf[2][BLOB];
    const int tid  = threadIdx.x;
    const int q    = tid & 3;            // hidden quarter
    const int m    = (tid >> 2) & 1;     // 0 = s-MLP, 1 = t-MLP
    const int slot = tid >> 3;           // 0..7 (4-node group)
    const int c    = blockIdx.y;
    // balanced node range for this block: [(bx*2048)/74, ((bx+1)*2048)/74)
    const int nstart = (blockIdx.x * 1024) / 37;
    const int nend   = ((blockIdx.x + 1) * 1024) / 37;

    int nidx[4];
    bool nval[4];
    #pragma unroll
    for (int n = 0; n < 4; n++) {
        int ni = nstart + slot * 4 + n;
        nval[n] = (ni < nend);
        nidx[n] = (ni < NN) ? ni : (NN - 1);   // clamp for safe reads
    }

    // z packed by parity: ze[j]=(dims 4j,4j+2), zo[j]=(4j+1,4j+3)
    ull ze[4][8], zo[4][8];
    #pragma unroll
    for (int n = 0; n < 4; n++) {
        const float4* np = (const float4*)(nodes + (size_t)nidx[n] * 32);
        #pragma unroll
        for (int j = 0; j < 8; j++) {
            float4 v = np[j];
            ze[n][j] = pack2(v.x, v.z); zo[n][j] = pack2(v.y, v.w);
        }
    }
    float ld[4] = {0.f, 0.f, 0.f, 0.f};

    const float* gb = g_blob + (size_t)(c * 64) * BLOB;

    stage(sbuf[0], gb + (size_t)63 * BLOB, tid);
    wait_stage();
    __syncthreads();

    #pragma unroll 1
    for (int k = 63; k > 0; k -= 2) {
        stage(sbuf[1], gb + (size_t)(k - 1) * BLOB, tid);
        // layer k (odd): active = odd dims
        layer_compute(sbuf[0], q, m, zo, ze, ld);
        wait_stage();
        __syncthreads();
        if (k >= 3) stage(sbuf[0], gb + (size_t)(k - 2) * BLOB, tid);
        // layer k-1 (even): active = even dims
        layer_compute(sbuf[1], q, m, ze, zo, ld);
        wait_stage();
        __syncthreads();
    }

    // DiagGaussian log_prob (redundant; written by q==0 && m==0, valid nodes)
    const float* lp = loc + c * 32;
    const float* sp = lsc + c * 32;
    #pragma unroll
    for (int n = 0; n < 4; n++) {
        float acc = 0.f;
        #pragma unroll
        for (int j = 0; j < 8; j++) {
            float e0, e1, o0, o1;
            unpack2(ze[n][j], e0, e1); unpack2(zo[n][j], o0, o1);
            float z4[4] = {e0, o0, e1, o1};
            #pragma unroll
            for (int b = 0; b < 4; b++) {
                int d = 4 * j + b;
                float ls = __ldg(sp + d);
                float u  = (z4[b] - __ldg(lp + d)) * __expf(-ls);
                acc += ls + 0.5f * u * u;
            }
        }
        if (q == 0 && m == 0 && nval[n])
            g_Bm[c * NN + nidx[n]] = __expf(ld[n] - 29.406037829f - acc);
    }
}

// Fold L1 row-normalizers and softmax-normalized S into one 8x8 matrix.
__global__ void norm_kernel(const float* __restrict__ S_unc)
{
    __shared__ float sh_r[8];
    __shared__ float sh_e[64];
    const int tid = threadIdx.x;
    const int w = tid >> 5, lane = tid & 31;

    float s = 0.f;
    for (int i = lane; i < NN; i += 32) s += g_Bm[w * NN + i];
    #pragma unroll
    for (int o = 16; o; o >>= 1) s += __shfl_xor_sync(0xffffffffu, s, o);
    if (lane == 0) sh_r[w] = fmaxf(s, 1e-12f);
    if (tid < 64) sh_e[tid] = expf(S_unc[tid]);
    __syncthreads();
    if (tid < 64) {
        float tot = 0.f;
        #pragma unroll
        for (int i = 0; i < 64; i++) tot += sh_e[i];
        int c1 = tid >> 3, c2 = tid & 7;
        g_Sn[tid] = sh_e[tid] / (tot * sh_r[c1] * sh_r[c2]);
    }
}

__global__ void __launch_bounds__(256)
out_kernel(float* __restrict__ out)
{
    __shared__ float B1[8][64];
    __shared__ float B2[8][64];
    __shared__ float T2[8][64];
    const int tid = threadIdx.x;
    const int n10 = blockIdx.y * 64;
    const int n20 = blockIdx.x * 64;

    for (int t = tid; t < 512; t += 256) {
        int cc = t >> 6, j = t & 63;
        B1[cc][j] = g_Bm[cc * NN + n10 + j];
        B2[cc][j] = g_Bm[cc * NN + n20 + j];
    }
    __syncthreads();
    if (tid < 64) {
        #pragma unroll
        for (int c1 = 0; c1 < 8; c1++) {
            float a = 0.f;
            #pragma unroll
            for (int c2 = 0; c2 < 8; c2++)
                a = fmaf(g_Sn[c1 * 8 + c2], B2[c2][tid], a);
            T2[c1][tid] = a;
        }
    }
    __syncthreads();

    const int ty = tid >> 4, tx = tid & 15;
    float bv[4][8], tv[8][4];
    #pragma unroll
    for (int cc = 0; cc < 8; cc++) {
        #pragma unroll
        for (int p = 0; p < 4; p++) {
            bv[p][cc] = B1[cc][ty * 4 + p];
            tv[cc][p] = T2[cc][tx * 4 + p];
        }
    }
    #pragma unroll
    for (int p = 0; p < 4; p++) {
        float4 o = {0.f, 0.f, 0.f, 0.f};
        #pragma unroll
        for (int cc = 0; cc < 8; cc++) {
            o.x = fmaf(bv[p][cc], tv[cc][0], o.x);
            o.y = fmaf(bv[p][cc], tv[cc][1], o.y);
            o.z = fmaf(bv[p][cc], tv[cc][2], o.z);
            o.w = fmaf(bv[p][cc], tv[cc][3], o.w);
        }
        *((float4*)(out + (size_t)(n10 + ty * 4 + p) * NN + n20 + tx * 4)) = o;
    }
}

extern "C" void kernel_launch(void* const* d_in, const int* in_sizes, int n_in,
                              void* d_out, int out_size)
{
    const float* nodes = (const float*)d_in[0];
    const float* sW1   = (const float*)d_in[1];
    const float* sb1   = (const float*)d_in[2];
    const float* sW2   = (const float*)d_in[3];
    const float* sb2   = (const float*)d_in[4];
    const float* tW1   = (const float*)d_in[5];
    const float* tb1   = (const float*)d_in[6];
    const float* tW2   = (const float*)d_in[7];
    const float* tb2   = (const float*)d_in[8];
    const float* anS   = (const float*)d_in[9];
    const float* anT   = (const float*)d_in[10];
    const float* loc   = (const float*)d_in[11];
    const float* lsc   = (const float*)d_in[12];
    const float* S_unc = (const float*)d_in[13];
    float* out = (float*)d_out;

    repack_kernel<<<C * K, 128>>>(sW1, sb1, sW2, sb2, tW1, tb1, tW2, tb2, anS, anT);
    dim3 fg(BPC, C);                     // 74 x 8 = 592 blocks = exactly 4/SM
    flow_kernel<<<fg, 64>>>(nodes, loc, lsc);
    norm_kernel<<<1, 256>>>(S_unc);
    dim3 og(NN / 64, NN / 64);
    out_kernel<<<og, 256>>>(out);
}